// round 8
// baseline (speedup 1.0000x reference)
#include <cuda_runtime.h>
#include <cuda_bf16.h>
#include <math.h>
#include <stdint.h>

// GCN1: 3-layer GCN over 4 graphs, shared weights, scalar-mean output.
// R7: bf16 feature storage for the SpMM gather (halves LTS-bound traffic),
//     fp32 accumulate + tf32 mma.sync GEMM (A stays fp32), layer-3 GEMM
//     is store-free (only the fused scalar sum matters).

#define NN 50000
#define EE 800000
#define FH 304
#define FI 128
#define NG 4
#define NB 196   // ceil(NN/256)

// ---------------- scratch (__device__ only; never passed as kernel args) ----
__device__ __align__(128) float    g_bufA[(size_t)NN * FH];        // SpMM out (fp32)
__device__ __align__(128) uint32_t g_bufBh[(size_t)NN * 152];      // GEMM out (bf16x2)
__device__ __align__(128) uint32_t g_xbf[NG][(size_t)NN * 64];     // x as bf16x2
__device__ __align__(128) float g_Wt1[320 * 128];   // [Npad=320][Kp]  K-major
__device__ __align__(128) float g_Wt2[320 * 320];
__device__ __align__(128) float g_Wt3[320 * 320];
__device__ float g_ns[NG][NN];
__device__ float g_nd[NG][NN];
__device__ int   g_deg_s[NG][NN];
__device__ int   g_deg_d[NG][NN];
__device__ int   g_rowoff[NG][NN + 1];
__device__ int   g_cursor[NG][NN];
__device__ int   g_csr[NG][EE];
__device__ int   g_bsum[NG][256];
__device__ int   g_boff[NG][256];
__device__ double g_sum;

// ---------------- small kernels ---------------------------------------------
__global__ void k_init() { g_sum = 0.0; }

// transpose W[K][FH] -> Wt[Npad=320][Kp], zero-padded in both dims
__global__ void k_prep_w(const float* __restrict__ W, int sel, int K, int Kp) {
    int id = blockIdx.x * blockDim.x + threadIdx.x;
    if (id >= 320 * Kp) return;
    int n = id / Kp, k = id % Kp;
    float v = (k < K && n < FH) ? W[(size_t)k * FH + n] : 0.f;
    float* dst = (sel == 0) ? g_Wt1 : (sel == 1) ? g_Wt2 : g_Wt3;
    dst[(size_t)n * Kp + k] = v;
}

// convert all 4 graphs' x to bf16x2, batched
__global__ void k_xconv(const float* __restrict__ x0, const float* __restrict__ x1,
                        const float* __restrict__ x2, const float* __restrict__ x3) {
    int g = blockIdx.y;
    const float* x = (g == 0) ? x0 : (g == 1) ? x1 : (g == 2) ? x2 : x3;
    int i = blockIdx.x * blockDim.x + threadIdx.x;   // pair index
    if (i < NN * 64) {
        float2 f = *(const float2*)(x + 2 * (size_t)i);
        __nv_bfloat162 b = __float22bfloat162_rn(f);
        g_xbf[g][i] = *(uint32_t*)&b;
    }
}

__global__ void k_zero() {
    int g = blockIdx.y;
    int i = blockIdx.x * blockDim.x + threadIdx.x;
    if (i < NN) { g_deg_s[g][i] = 0; g_deg_d[g][i] = 0; }
}

__global__ void k_deg(const int* __restrict__ s0, const int* __restrict__ d0,
                      const int* __restrict__ s1, const int* __restrict__ d1,
                      const int* __restrict__ s2, const int* __restrict__ d2,
                      const int* __restrict__ s3, const int* __restrict__ d3) {
    int g = blockIdx.y;
    const int* s = (g == 0) ? s0 : (g == 1) ? s1 : (g == 2) ? s2 : s3;
    const int* d = (g == 0) ? d0 : (g == 1) ? d1 : (g == 2) ? d2 : d3;
    int e = blockIdx.x * blockDim.x + threadIdx.x;
    if (e < EE) {
        atomicAdd(&g_deg_s[g][s[e]], 1);
        atomicAdd(&g_deg_d[g][d[e]], 1);
    }
}

__global__ void k_scan1() {
    int g = blockIdx.y, t = threadIdx.x;
    int i = blockIdx.x * 256 + t;
    __shared__ int sm[256];
    sm[t] = (i < NN) ? g_deg_d[g][i] : 0;
    __syncthreads();
    for (int o = 128; o > 0; o >>= 1) {
        if (t < o) sm[t] += sm[t + o];
        __syncthreads();
    }
    if (t == 0) g_bsum[g][blockIdx.x] = sm[0];
}

__global__ void k_scan2() {
    int g = blockIdx.y, t = threadIdx.x;
    int v = (t < NB) ? g_bsum[g][t] : 0;
    __shared__ int sm[256];
    sm[t] = v;
    __syncthreads();
    for (int o = 1; o < 256; o <<= 1) {
        int a = (t >= o) ? sm[t - o] : 0;
        __syncthreads();
        sm[t] += a;
        __syncthreads();
    }
    g_boff[g][t] = sm[t] - v;  // exclusive
}

__global__ void k_scan3() {
    int g = blockIdx.y, t = threadIdx.x;
    int i = blockIdx.x * 256 + t;
    int d = (i < NN) ? g_deg_d[g][i] : 0;
    __shared__ int sm[256];
    sm[t] = d;
    __syncthreads();
    for (int o = 1; o < 256; o <<= 1) {
        int a = (t >= o) ? sm[t - o] : 0;
        __syncthreads();
        sm[t] += a;
        __syncthreads();
    }
    int off = g_boff[g][blockIdx.x] + sm[t] - d;  // exclusive
    if (i < NN) {
        g_rowoff[g][i] = off;
        g_cursor[g][i] = off;
        g_nd[g][i] = rsqrtf((float)max(d, 1));
        g_ns[g][i] = rsqrtf((float)max(g_deg_s[g][i], 1));
    }
    if (blockIdx.x == 0 && t == 0) g_rowoff[g][NN] = EE;
}

__global__ void k_scatter(const int* __restrict__ s0, const int* __restrict__ d0,
                          const int* __restrict__ s1, const int* __restrict__ d1,
                          const int* __restrict__ s2, const int* __restrict__ d2,
                          const int* __restrict__ s3, const int* __restrict__ d3) {
    int g = blockIdx.y;
    const int* s = (g == 0) ? s0 : (g == 1) ? s1 : (g == 2) ? s2 : s3;
    const int* d = (g == 0) ? d0 : (g == 1) ? d1 : (g == 2) ? d2 : d3;
    int e = blockIdx.x * blockDim.x + threadIdx.x;
    if (e < EE) {
        int p = atomicAdd(&g_cursor[g][d[e]], 1);
        g_csr[g][p] = s[e];
    }
}

// Block-per-dst SpMM over bf16x2 features, fp32 accumulate, fp32 output:
// g_bufA[n][:] = nd[n] * sum_{s in in(n)} ns[s] * hin[s][:]
// F2 = feature pairs per row (64 or 152). blockDim = 64 (layer1) or 128.
__global__ void k_spmm(int g, int F2, int layer1) {
    const uint32_t* __restrict__ hin = layer1 ? g_xbf[g] : g_bufBh;
    int n = blockIdx.x;
    int t = threadIdx.x;
    int bs = blockDim.x;
    int beg = g_rowoff[g][n];
    int end = g_rowoff[g][n + 1];
    float2 acc[2];
    acc[0] = make_float2(0.f, 0.f);
    acc[1] = make_float2(0.f, 0.f);
    int j = beg;
    for (; j + 1 < end; j += 2) {
        int sA = g_csr[g][j], sB = g_csr[g][j + 1];
        float wA = g_ns[g][sA], wB = g_ns[g][sB];
        const uint32_t* rA = hin + (size_t)sA * F2;
        const uint32_t* rB = hin + (size_t)sB * F2;
#pragma unroll
        for (int i = 0; i < 2; i++) {
            int p = t + i * bs;
            if (p < F2) {
                uint32_t uA = rA[p], uB = rB[p];
                float2 fA = __bfloat1622float2(*(__nv_bfloat162*)&uA);
                float2 fB = __bfloat1622float2(*(__nv_bfloat162*)&uB);
                acc[i].x += wA * fA.x + wB * fB.x;
                acc[i].y += wA * fA.y + wB * fB.y;
            }
        }
    }
    if (j < end) {
        int s = g_csr[g][j];
        float w = g_ns[g][s];
        const uint32_t* r = hin + (size_t)s * F2;
#pragma unroll
        for (int i = 0; i < 2; i++) {
            int p = t + i * bs;
            if (p < F2) {
                uint32_t u = r[p];
                float2 f = __bfloat1622float2(*(__nv_bfloat162*)&u);
                acc[i].x += w * f.x;
                acc[i].y += w * f.y;
            }
        }
    }
    float nd = g_nd[g][n];
    int F = 2 * F2;
#pragma unroll
    for (int i = 0; i < 2; i++) {
        int p = t + i * bs;
        if (p < F2)
            *(float2*)(g_bufA + (size_t)n * F + 2 * p) =
                make_float2(acc[i].x * nd, acc[i].y * nd);
    }
}

// ---------------- tf32 mma.sync GEMM ----------------------------------------
// relu(g_bufA[.,K] @ Wt^T + bias) -> g_bufBh (bf16x2), or (dosum) only the
// fp32 scalar sum (no store). CTA: 256 thr (8 warps 4x2), tile 128x64, BK=32.
__device__ __forceinline__ uint32_t f2tf32(float v) {
    uint32_t o;
    asm("cvt.rna.tf32.f32 %0, %1;" : "=r"(o) : "f"(v));
    return o;
}
__device__ __forceinline__ void mma8(float* d, const uint32_t* a, const uint32_t* b) {
    asm volatile("mma.sync.aligned.m16n8k8.row.col.f32.tf32.tf32.f32 "
                 "{%0,%1,%2,%3}, {%4,%5,%6,%7}, {%8,%9}, {%0,%1,%2,%3};"
                 : "+f"(d[0]), "+f"(d[1]), "+f"(d[2]), "+f"(d[3])
                 : "r"(a[0]), "r"(a[1]), "r"(a[2]), "r"(a[3]),
                   "r"(b[0]), "r"(b[1]));
}

#define PADK 36  // 32 + 4 pad: fragment LDS bank-conflict-free

__global__ void __launch_bounds__(256)
k_gemm_mma(const float* __restrict__ bias, int wsel, int K, int NC, int dosum) {
    __shared__ uint32_t As[128][PADK];
    __shared__ uint32_t Bs[64][PADK];
    __shared__ float wsum[8];

    const float* __restrict__ Wt = (wsel == 0) ? g_Wt1 : (wsel == 1) ? g_Wt2 : g_Wt3;
    const int Kp = NC * 32;
    const int astride = K;

    int tid = threadIdx.x, wid = tid >> 5, lane = tid & 31;
    int wm = wid & 3, wn = wid >> 2;
    int rowBase = blockIdx.x * 128;
    int colBase = blockIdx.y * 64;

    float acc[2][4][4];
#pragma unroll
    for (int mi = 0; mi < 2; mi++)
#pragma unroll
        for (int ni = 0; ni < 4; ni++)
#pragma unroll
            for (int q = 0; q < 4; q++) acc[mi][ni][q] = 0.f;

    int arow = tid >> 3, aq = tid & 7;
    int brow = tid >> 3, bq = tid & 7;
    float4 aR[4], bR[2];

    {   // prefetch chunk 0
        int k0 = 0;
#pragma unroll
        for (int j = 0; j < 4; j++) {
            int r = arow + j * 32, gr = rowBase + r, kf = k0 + aq * 4;
            aR[j] = (gr < NN && kf < K)
                ? *(const float4*)(g_bufA + (size_t)gr * astride + kf)
                : make_float4(0.f, 0.f, 0.f, 0.f);
        }
#pragma unroll
        for (int j = 0; j < 2; j++) {
            int r = brow + j * 32, gn = colBase + r;
            bR[j] = *(const float4*)(Wt + (size_t)gn * Kp + k0 + bq * 4);
        }
    }

    for (int c = 0; c < NC; c++) {
#pragma unroll
        for (int j = 0; j < 4; j++) {
            uint32_t* p = &As[arow + j * 32][aq * 4];
            p[0] = f2tf32(aR[j].x); p[1] = f2tf32(aR[j].y);
            p[2] = f2tf32(aR[j].z); p[3] = f2tf32(aR[j].w);
        }
#pragma unroll
        for (int j = 0; j < 2; j++) {
            uint32_t* p = &Bs[brow + j * 32][bq * 4];
            p[0] = f2tf32(bR[j].x); p[1] = f2tf32(bR[j].y);
            p[2] = f2tf32(bR[j].z); p[3] = f2tf32(bR[j].w);
        }
        __syncthreads();

        if (c + 1 < NC) {
            int k0 = (c + 1) * 32;
#pragma unroll
            for (int j = 0; j < 4; j++) {
                int r = arow + j * 32, gr = rowBase + r, kf = k0 + aq * 4;
                aR[j] = (gr < NN && kf < K)
                    ? *(const float4*)(g_bufA + (size_t)gr * astride + kf)
                    : make_float4(0.f, 0.f, 0.f, 0.f);
            }
#pragma unroll
            for (int j = 0; j < 2; j++) {
                int r = brow + j * 32, gn = colBase + r;
                bR[j] = *(const float4*)(Wt + (size_t)gn * Kp + k0 + bq * 4);
            }
        }

        int g = lane >> 2, cc = lane & 3;
#pragma unroll
        for (int kk = 0; kk < 32; kk += 8) {
            uint32_t af[2][4], bf[4][2];
#pragma unroll
            for (int mi = 0; mi < 2; mi++) {
                int base = wm * 32 + mi * 16 + g;
                af[mi][0] = As[base][kk + cc];
                af[mi][1] = As[base + 8][kk + cc];
                af[mi][2] = As[base][kk + cc + 4];
                af[mi][3] = As[base + 8][kk + cc + 4];
            }
#pragma unroll
            for (int ni = 0; ni < 4; ni++) {
                int nb = wn * 32 + ni * 8 + g;
                bf[ni][0] = Bs[nb][kk + cc];
                bf[ni][1] = Bs[nb][kk + cc + 4];
            }
#pragma unroll
            for (int mi = 0; mi < 2; mi++)
#pragma unroll
                for (int ni = 0; ni < 4; ni++)
                    mma8(acc[mi][ni], af[mi], bf[ni]);
        }
        __syncthreads();
    }

    // epilogue: bias + relu; store bf16x2 (layers 1-2) or fp32 sum only (layer 3)
    float lsum = 0.f;
    int g = lane >> 2, cc = lane & 3;
#pragma unroll
    for (int mi = 0; mi < 2; mi++) {
        int r0 = rowBase + wm * 32 + mi * 16 + g;
#pragma unroll
        for (int ni = 0; ni < 4; ni++) {
            int c0 = colBase + wn * 32 + ni * 8 + cc * 2;
            if (c0 < FH) {
                float bz0 = bias[c0], bz1 = bias[c0 + 1];
                float v0 = fmaxf(acc[mi][ni][0] + bz0, 0.f);
                float v1 = fmaxf(acc[mi][ni][1] + bz1, 0.f);
                float v2 = fmaxf(acc[mi][ni][2] + bz0, 0.f);
                float v3 = fmaxf(acc[mi][ni][3] + bz1, 0.f);
                if (dosum) {
                    if (r0 < NN)     lsum += v0 + v1;
                    if (r0 + 8 < NN) lsum += v2 + v3;
                } else {
                    if (r0 < NN) {
                        __nv_bfloat162 b = __float22bfloat162_rn(make_float2(v0, v1));
                        g_bufBh[(size_t)r0 * 152 + (c0 >> 1)] = *(uint32_t*)&b;
                    }
                    if (r0 + 8 < NN) {
                        __nv_bfloat162 b = __float22bfloat162_rn(make_float2(v2, v3));
                        g_bufBh[(size_t)(r0 + 8) * 152 + (c0 >> 1)] = *(uint32_t*)&b;
                    }
                }
            }
        }
    }
    if (dosum) {
#pragma unroll
        for (int o = 16; o > 0; o >>= 1) lsum += __shfl_down_sync(0xffffffffu, lsum, o);
        if (lane == 0) wsum[wid] = lsum;
        __syncthreads();
        if (tid == 0) {
            double tot = 0.0;
#pragma unroll
            for (int w = 0; w < 8; w++) tot += (double)wsum[w];
            atomicAdd(&g_sum, tot);
        }
    }
}

__global__ void k_final(float* __restrict__ out) {
    out[0] = (float)(g_sum / (4.0 * NN * FH));
}

// ---------------- launch -----------------------------------------------------
extern "C" void kernel_launch(void* const* d_in, const int* in_sizes, int n_in,
                              void* d_out, int out_size) {
    const float* X[4];   int nx = 0;
    const int*   EDG[8]; int ne = 0;
    const float* W[3] = {0, 0, 0};
    const float* Bv[3]; int nb = 0;
    int nw2 = 0;
    for (int i = 0; i < n_in; i++) {
        int sz = in_sizes[i];
        if (sz == 6400000)      X[nx++]   = (const float*)d_in[i];
        else if (sz == 800000)  EDG[ne++] = (const int*)d_in[i];
        else if (sz == 38912)   W[0] = (const float*)d_in[i];
        else if (sz == 92416)   { W[1 + nw2] = (const float*)d_in[i]; nw2++; }
        else if (sz == 304)     Bv[nb++] = (const float*)d_in[i];
    }
    float* out = (float*)d_out;

    k_init<<<1, 1>>>();
    k_prep_w<<<(320 * 128 + 255) / 256, 256>>>(W[0], 0, 128, 128);
    k_prep_w<<<(320 * 320 + 255) / 256, 256>>>(W[1], 1, 304, 320);
    k_prep_w<<<(320 * 320 + 255) / 256, 256>>>(W[2], 2, 304, 320);
    k_xconv<<<dim3((NN * 64 + 255) / 256, NG), 256>>>(X[0], X[1], X[2], X[3]);

    // batched CSR build for all 4 graphs
    k_zero<<<dim3(NB, NG), 256>>>();
    k_deg<<<dim3(EE / 256, NG), 256>>>(EDG[0], EDG[1], EDG[2], EDG[3],
                                       EDG[4], EDG[5], EDG[6], EDG[7]);
    k_scan1<<<dim3(NB, NG), 256>>>();
    k_scan2<<<dim3(1, NG), 256>>>();
    k_scan3<<<dim3(NB, NG), 256>>>();
    k_scatter<<<dim3(EE / 256, NG), 256>>>(EDG[0], EDG[1], EDG[2], EDG[3],
                                           EDG[4], EDG[5], EDG[6], EDG[7]);

    dim3 gemmGrid((NN + 127) / 128, 5);  // N padded to 320
    for (int g = 0; g < 4; g++) {
        k_spmm<<<NN, 64>>>(g, 64, 1);                       // layer 1 aggregate
        k_gemm_mma<<<gemmGrid, 256>>>(Bv[0], 0, 128, 4, 0);
        k_spmm<<<NN, 128>>>(g, 152, 0);                     // layer 2 aggregate
        k_gemm_mma<<<gemmGrid, 256>>>(Bv[1], 1, 304, 10, 0);
        k_spmm<<<NN, 128>>>(g, 152, 0);                     // layer 3 aggregate
        k_gemm_mma<<<gemmGrid, 256>>>(Bv[2], 2, 304, 10, 1);
    }
    k_final<<<1, 1>>>(out);
}

// round 9
// speedup vs baseline: 1.1962x; 1.1962x over previous
#include <cuda_runtime.h>
#include <cuda_bf16.h>
#include <math.h>
#include <stdint.h>

// GCN1: 3-layer GCN over 4 graphs, shared weights, scalar-mean output.
// R9: revert SpMM to fp32 (R6 form; bf16 gather was a latency-bound loss),
//     GEMM -> bf16 mma.sync m16n8k16 (2x k per mma), weights pre-packed
//     bf16x2, layer-3 GEMM store-free (fused scalar sum only).

#define NN 50000
#define EE 800000
#define FH 304
#define FI 128
#define NG 4
#define NB 196   // ceil(NN/256)

// ---------------- scratch (__device__ only; never passed as kernel args) ----
__device__ __align__(128) float g_bufA[(size_t)NN * FH];   // SpMM out (fp32)
__device__ __align__(128) float g_bufB[(size_t)NN * FH];   // GEMM out (fp32)
__device__ __align__(128) uint32_t g_Wh1[320 * 64];        // [Npad][Kp/2] bf16x2
__device__ __align__(128) uint32_t g_Wh2[320 * 160];
__device__ __align__(128) uint32_t g_Wh3[320 * 160];
__device__ float g_ns[NG][NN];
__device__ float g_nd[NG][NN];
__device__ int   g_deg_s[NG][NN];
__device__ int   g_deg_d[NG][NN];
__device__ int   g_rowoff[NG][NN + 1];
__device__ int   g_cursor[NG][NN];
__device__ int   g_csr[NG][EE];
__device__ int   g_bsum[NG][256];
__device__ int   g_boff[NG][256];
__device__ double g_sum;

// ---------------- small kernels ---------------------------------------------
__global__ void k_init() { g_sum = 0.0; }

// W[K][FH] -> Wh[Npad=320][Kp/2] packed bf16x2 (k even = low half), zero-pad
__global__ void k_prep_wh(const float* __restrict__ W, int sel, int K, int Kp2) {
    int id = blockIdx.x * blockDim.x + threadIdx.x;
    if (id >= 320 * Kp2) return;
    int n = id / Kp2, kw = id % Kp2;
    int k = 2 * kw;
    float v0 = (k < K && n < FH) ? W[(size_t)k * FH + n] : 0.f;
    float v1 = (k + 1 < K && n < FH) ? W[(size_t)(k + 1) * FH + n] : 0.f;
    __nv_bfloat162 b = __float22bfloat162_rn(make_float2(v0, v1));
    uint32_t* dst = (sel == 0) ? g_Wh1 : (sel == 1) ? g_Wh2 : g_Wh3;
    dst[(size_t)n * Kp2 + kw] = *(uint32_t*)&b;
}

__global__ void k_zero() {
    int g = blockIdx.y;
    int i = blockIdx.x * blockDim.x + threadIdx.x;
    if (i < NN) { g_deg_s[g][i] = 0; g_deg_d[g][i] = 0; }
}

__global__ void k_deg(const int* __restrict__ s0, const int* __restrict__ d0,
                      const int* __restrict__ s1, const int* __restrict__ d1,
                      const int* __restrict__ s2, const int* __restrict__ d2,
                      const int* __restrict__ s3, const int* __restrict__ d3) {
    int g = blockIdx.y;
    const int* s = (g == 0) ? s0 : (g == 1) ? s1 : (g == 2) ? s2 : s3;
    const int* d = (g == 0) ? d0 : (g == 1) ? d1 : (g == 2) ? d2 : d3;
    int e = blockIdx.x * blockDim.x + threadIdx.x;
    if (e < EE) {
        atomicAdd(&g_deg_s[g][s[e]], 1);
        atomicAdd(&g_deg_d[g][d[e]], 1);
    }
}

__global__ void k_scan1() {
    int g = blockIdx.y, t = threadIdx.x;
    int i = blockIdx.x * 256 + t;
    __shared__ int sm[256];
    sm[t] = (i < NN) ? g_deg_d[g][i] : 0;
    __syncthreads();
    for (int o = 128; o > 0; o >>= 1) {
        if (t < o) sm[t] += sm[t + o];
        __syncthreads();
    }
    if (t == 0) g_bsum[g][blockIdx.x] = sm[0];
}

__global__ void k_scan2() {
    int g = blockIdx.y, t = threadIdx.x;
    int v = (t < NB) ? g_bsum[g][t] : 0;
    __shared__ int sm[256];
    sm[t] = v;
    __syncthreads();
    for (int o = 1; o < 256; o <<= 1) {
        int a = (t >= o) ? sm[t - o] : 0;
        __syncthreads();
        sm[t] += a;
        __syncthreads();
    }
    g_boff[g][t] = sm[t] - v;  // exclusive
}

__global__ void k_scan3() {
    int g = blockIdx.y, t = threadIdx.x;
    int i = blockIdx.x * 256 + t;
    int d = (i < NN) ? g_deg_d[g][i] : 0;
    __shared__ int sm[256];
    sm[t] = d;
    __syncthreads();
    for (int o = 1; o < 256; o <<= 1) {
        int a = (t >= o) ? sm[t - o] : 0;
        __syncthreads();
        sm[t] += a;
        __syncthreads();
    }
    int off = g_boff[g][blockIdx.x] + sm[t] - d;  // exclusive
    if (i < NN) {
        g_rowoff[g][i] = off;
        g_cursor[g][i] = off;
        g_nd[g][i] = rsqrtf((float)max(d, 1));
        g_ns[g][i] = rsqrtf((float)max(g_deg_s[g][i], 1));
    }
    if (blockIdx.x == 0 && t == 0) g_rowoff[g][NN] = EE;
}

__global__ void k_scatter(const int* __restrict__ s0, const int* __restrict__ d0,
                          const int* __restrict__ s1, const int* __restrict__ d1,
                          const int* __restrict__ s2, const int* __restrict__ d2,
                          const int* __restrict__ s3, const int* __restrict__ d3) {
    int g = blockIdx.y;
    const int* s = (g == 0) ? s0 : (g == 1) ? s1 : (g == 2) ? s2 : s3;
    const int* d = (g == 0) ? d0 : (g == 1) ? d1 : (g == 2) ? d2 : d3;
    int e = blockIdx.x * blockDim.x + threadIdx.x;
    if (e < EE) {
        int p = atomicAdd(&g_cursor[g][d[e]], 1);
        g_csr[g][p] = s[e];
    }
}

// Block-per-dst SpMM (fp32, R6 form): g_bufA[n][:] = nd[n]*sum ns[s]*hin[s][:]
__global__ void k_spmm(const float* __restrict__ xext, int use_ext, int F, int g) {
    const float* __restrict__ hin = use_ext ? xext : (const float*)g_bufB;
    int n = blockIdx.x;
    int t = threadIdx.x;
    int beg = g_rowoff[g][n];
    int end = g_rowoff[g][n + 1];
    float acc0 = 0.f, acc1 = 0.f, acc2 = 0.f;
    int j = beg;
    for (; j + 1 < end; j += 2) {
        int sA = g_csr[g][j], sB = g_csr[g][j + 1];
        float wA = g_ns[g][sA], wB = g_ns[g][sB];
        const float* rA = hin + (size_t)sA * F;
        const float* rB = hin + (size_t)sB * F;
        acc0 += wA * rA[t] + wB * rB[t];
        if (F > 128) {
            acc1 += wA * rA[t + 128] + wB * rB[t + 128];
            if (t + 256 < F) acc2 += wA * rA[t + 256] + wB * rB[t + 256];
        }
    }
    if (j < end) {
        int s = g_csr[g][j];
        float w = g_ns[g][s];
        const float* r = hin + (size_t)s * F;
        acc0 += w * r[t];
        if (F > 128) {
            acc1 += w * r[t + 128];
            if (t + 256 < F) acc2 += w * r[t + 256];
        }
    }
    float nd = g_nd[g][n];
    float* o = g_bufA + (size_t)n * F;
    o[t] = acc0 * nd;
    if (F > 128) {
        o[t + 128] = acc1 * nd;
        if (t + 256 < F) o[t + 256] = acc2 * nd;
    }
}

// ---------------- bf16 mma.sync GEMM ----------------------------------------
// relu(g_bufA[.,K] @ Wh^T + bias) -> g_bufB fp32, or (dosum) scalar sum only.
// CTA: 256 thr (8 warps 4x2), tile 128x64, BK=32 (two k16 steps per chunk).
__device__ __forceinline__ void mma16(float* d, const uint32_t* a, const uint32_t* b) {
    asm volatile("mma.sync.aligned.m16n8k16.row.col.f32.bf16.bf16.f32 "
                 "{%0,%1,%2,%3}, {%4,%5,%6,%7}, {%8,%9}, {%0,%1,%2,%3};"
                 : "+f"(d[0]), "+f"(d[1]), "+f"(d[2]), "+f"(d[3])
                 : "r"(a[0]), "r"(a[1]), "r"(a[2]), "r"(a[3]),
                   "r"(b[0]), "r"(b[1]));
}
__device__ __forceinline__ uint32_t packbf(float x, float y) {
    __nv_bfloat162 b = __float22bfloat162_rn(make_float2(x, y));
    return *(uint32_t*)&b;
}

#define PADW 20  // 16 words + 4 pad: (g*20 + c) mod 32 disjoint per lane group

__global__ void __launch_bounds__(256)
k_gemm_mma(const float* __restrict__ bias, int wsel, int K, int NC, int dosum) {
    __shared__ uint32_t As[128][PADW];   // bf16x2 words along k
    __shared__ uint32_t Bs[64][PADW];
    __shared__ float wsum[8];

    const uint32_t* __restrict__ Wh = (wsel == 0) ? g_Wh1 : (wsel == 1) ? g_Wh2 : g_Wh3;
    const int Kp2 = NC * 16;   // words per weight row
    const int astride = K;

    int tid = threadIdx.x, wid = tid >> 5, lane = tid & 31;
    int wm = wid & 3, wn = wid >> 2;
    int rowBase = blockIdx.x * 128;
    int colBase = blockIdx.y * 64;

    float acc[2][4][4];
#pragma unroll
    for (int mi = 0; mi < 2; mi++)
#pragma unroll
        for (int ni = 0; ni < 4; ni++)
#pragma unroll
            for (int q = 0; q < 4; q++) acc[mi][ni][q] = 0.f;

    int arow = tid >> 3, aq = tid & 7;   // A: 4 float4 per thread (rows +0,32,64,96)
    int brow = tid >> 2, bq = tid & 3;   // B: 1 uint4 per thread (4 words)
    float4 aR[4];
    uint4  bRu;

    {   // prefetch chunk 0
#pragma unroll
        for (int j = 0; j < 4; j++) {
            int gr = rowBase + arow + j * 32, kf = aq * 4;
            aR[j] = (gr < NN && kf < K)
                ? *(const float4*)(g_bufA + (size_t)gr * astride + kf)
                : make_float4(0.f, 0.f, 0.f, 0.f);
        }
        bRu = *(const uint4*)(Wh + (size_t)(colBase + brow) * Kp2 + bq * 4);
    }

    for (int c = 0; c < NC; c++) {
        // store prefetched regs to SMEM (A: fp32 -> packed bf16x2)
#pragma unroll
        for (int j = 0; j < 4; j++) {
            uint32_t* p = &As[arow + j * 32][aq * 2];
            p[0] = packbf(aR[j].x, aR[j].y);
            p[1] = packbf(aR[j].z, aR[j].w);
        }
        {
            uint32_t* p = &Bs[brow][bq * 4];
            p[0] = bRu.x; p[1] = bRu.y; p[2] = bRu.z; p[3] = bRu.w;
        }
        __syncthreads();

        // issue global loads for next chunk
        if (c + 1 < NC) {
            int k0 = (c + 1) * 32;
#pragma unroll
            for (int j = 0; j < 4; j++) {
                int gr = rowBase + arow + j * 32, kf = k0 + aq * 4;
                aR[j] = (gr < NN && kf < K)
                    ? *(const float4*)(g_bufA + (size_t)gr * astride + kf)
                    : make_float4(0.f, 0.f, 0.f, 0.f);
            }
            bRu = *(const uint4*)(Wh + (size_t)(colBase + brow) * Kp2
                                  + (c + 1) * 16 + bq * 4);
        }

        // compute: two k16 steps (word offsets 0 and 8)
        int g = lane >> 2, cc = lane & 3;
#pragma unroll
        for (int kw = 0; kw < 16; kw += 8) {
            uint32_t af[2][4], bf[4][2];
#pragma unroll
            for (int mi = 0; mi < 2; mi++) {
                int base = wm * 32 + mi * 16 + g;
                af[mi][0] = As[base][kw + cc];
                af[mi][1] = As[base + 8][kw + cc];
                af[mi][2] = As[base][kw + cc + 4];
                af[mi][3] = As[base + 8][kw + cc + 4];
            }
#pragma unroll
            for (int ni = 0; ni < 4; ni++) {
                int nb = wn * 32 + ni * 8 + g;
                bf[ni][0] = Bs[nb][kw + cc];
                bf[ni][1] = Bs[nb][kw + cc + 4];
            }
#pragma unroll
            for (int mi = 0; mi < 2; mi++)
#pragma unroll
                for (int ni = 0; ni < 4; ni++)
                    mma16(acc[mi][ni], af[mi], bf[ni]);
        }
        __syncthreads();
    }

    // epilogue: bias + relu; store fp32 (layers 1-2) or scalar sum only (layer 3)
    float lsum = 0.f;
    int g = lane >> 2, cc = lane & 3;
#pragma unroll
    for (int mi = 0; mi < 2; mi++) {
        int r0 = rowBase + wm * 32 + mi * 16 + g;
#pragma unroll
        for (int ni = 0; ni < 4; ni++) {
            int c0 = colBase + wn * 32 + ni * 8 + cc * 2;
            if (c0 < FH) {
                float bz0 = bias[c0], bz1 = bias[c0 + 1];
                float v0 = fmaxf(acc[mi][ni][0] + bz0, 0.f);
                float v1 = fmaxf(acc[mi][ni][1] + bz1, 0.f);
                float v2 = fmaxf(acc[mi][ni][2] + bz0, 0.f);
                float v3 = fmaxf(acc[mi][ni][3] + bz1, 0.f);
                if (dosum) {
                    if (r0 < NN)     lsum += v0 + v1;
                    if (r0 + 8 < NN) lsum += v2 + v3;
                } else {
                    if (r0 < NN)
                        *(float2*)(g_bufB + (size_t)r0 * FH + c0) = make_float2(v0, v1);
                    if (r0 + 8 < NN)
                        *(float2*)(g_bufB + (size_t)(r0 + 8) * FH + c0) = make_float2(v2, v3);
                }
            }
        }
    }
    if (dosum) {
#pragma unroll
        for (int o = 16; o > 0; o >>= 1) lsum += __shfl_down_sync(0xffffffffu, lsum, o);
        if (lane == 0) wsum[wid] = lsum;
        __syncthreads();
        if (tid == 0) {
            double tot = 0.0;
#pragma unroll
            for (int w = 0; w < 8; w++) tot += (double)wsum[w];
            atomicAdd(&g_sum, tot);
        }
    }
}

__global__ void k_final(float* __restrict__ out) {
    out[0] = (float)(g_sum / (4.0 * NN * FH));
}

// ---------------- launch -----------------------------------------------------
extern "C" void kernel_launch(void* const* d_in, const int* in_sizes, int n_in,
                              void* d_out, int out_size) {
    const float* X[4];   int nx = 0;
    const int*   EDG[8]; int ne = 0;
    const float* W[3] = {0, 0, 0};
    const float* Bv[3]; int nb = 0;
    int nw2 = 0;
    for (int i = 0; i < n_in; i++) {
        int sz = in_sizes[i];
        if (sz == 6400000)      X[nx++]   = (const float*)d_in[i];
        else if (sz == 800000)  EDG[ne++] = (const int*)d_in[i];
        else if (sz == 38912)   W[0] = (const float*)d_in[i];
        else if (sz == 92416)   { W[1 + nw2] = (const float*)d_in[i]; nw2++; }
        else if (sz == 304)     Bv[nb++] = (const float*)d_in[i];
    }
    float* out = (float*)d_out;

    k_init<<<1, 1>>>();
    k_prep_wh<<<(320 * 64 + 255) / 256, 256>>>(W[0], 0, 128, 64);
    k_prep_wh<<<(320 * 160 + 255) / 256, 256>>>(W[1], 1, 304, 160);
    k_prep_wh<<<(320 * 160 + 255) / 256, 256>>>(W[2], 2, 304, 160);

    // batched CSR build for all 4 graphs
    k_zero<<<dim3(NB, NG), 256>>>();
    k_deg<<<dim3(EE / 256, NG), 256>>>(EDG[0], EDG[1], EDG[2], EDG[3],
                                       EDG[4], EDG[5], EDG[6], EDG[7]);
    k_scan1<<<dim3(NB, NG), 256>>>();
    k_scan2<<<dim3(1, NG), 256>>>();
    k_scan3<<<dim3(NB, NG), 256>>>();
    k_scatter<<<dim3(EE / 256, NG), 256>>>(EDG[0], EDG[1], EDG[2], EDG[3],
                                           EDG[4], EDG[5], EDG[6], EDG[7]);

    dim3 gemmGrid((NN + 127) / 128, 5);  // N padded to 320
    for (int g = 0; g < 4; g++) {
        k_spmm<<<NN, 128>>>(X[g], 1, FI, g);
        k_gemm_mma<<<gemmGrid, 256>>>(Bv[0], 0, 128, 4, 0);
        k_spmm<<<NN, 128>>>(X[g], 0, FH, g);
        k_gemm_mma<<<gemmGrid, 256>>>(Bv[1], 1, 304, 10, 0);
        k_spmm<<<NN, 128>>>(X[g], 0, FH, g);
        k_gemm_mma<<<gemmGrid, 256>>>(Bv[2], 2, 304, 10, 1);
    }
    k_final<<<1, 1>>>(out);
}

// round 11
// speedup vs baseline: 1.5646x; 1.3079x over previous
#include <cuda_runtime.h>
#include <cuda_bf16.h>
#include <math.h>
#include <stdint.h>

// GCN1: 3-layer GCN over 4 graphs, shared weights, scalar-mean output.
// R10: warp-per-dst float4 SpMM (LDG.128: 4x fewer load instrs -- the SpMM
//      was LSU-issue-floor bound, not byte bound), SpMM emits packed bf16x2
//      (numerically identical to R9's GEMM-side pack), GEMM A path is bf16.

#define NN 50000
#define EE 800000
#define FH 304
#define FI 128
#define NG 4
#define NB 196   // ceil(NN/256)

// ---------------- scratch (__device__ only; never passed as kernel args) ----
__device__ __align__(128) uint32_t g_bufAh[(size_t)NN * 160]; // SpMM out bf16x2, padded rows
__device__ __align__(128) float    g_bufB[(size_t)NN * FH];   // GEMM out (fp32)
__device__ __align__(128) uint32_t g_Wh1[320 * 64];           // [Npad][K/2] bf16x2
__device__ __align__(128) uint32_t g_Wh2[320 * 160];
__device__ __align__(128) uint32_t g_Wh3[320 * 160];
__device__ float g_ns[NG][NN];
__device__ float g_nd[NG][NN];
__device__ int   g_deg_s[NG][NN];
__device__ int   g_deg_d[NG][NN];
__device__ int   g_rowoff[NG][NN + 1];
__device__ int   g_cursor[NG][NN];
__device__ int   g_csr[NG][EE];
__device__ int   g_bsum[NG][256];
__device__ int   g_boff[NG][256];
__device__ double g_sum;

// ---------------- small kernels ---------------------------------------------
__global__ void k_init() { g_sum = 0.0; }

// W[K][FH] -> Wh[Npad=320][Kp/2] packed bf16x2, zero-padded
__global__ void k_prep_wh(const float* __restrict__ W, int sel, int K, int Kp2) {
    int id = blockIdx.x * blockDim.x + threadIdx.x;
    if (id >= 320 * Kp2) return;
    int n = id / Kp2, kw = id % Kp2;
    int k = 2 * kw;
    float v0 = (k < K && n < FH) ? W[(size_t)k * FH + n] : 0.f;
    float v1 = (k + 1 < K && n < FH) ? W[(size_t)(k + 1) * FH + n] : 0.f;
    __nv_bfloat162 b = __float22bfloat162_rn(make_float2(v0, v1));
    uint32_t* dst = (sel == 0) ? g_Wh1 : (sel == 1) ? g_Wh2 : g_Wh3;
    dst[(size_t)n * Kp2 + kw] = *(uint32_t*)&b;
}

__global__ void k_zero() {
    int g = blockIdx.y;
    int i = blockIdx.x * blockDim.x + threadIdx.x;
    if (i < NN) { g_deg_s[g][i] = 0; g_deg_d[g][i] = 0; }
}

__global__ void k_deg(const int* __restrict__ s0, const int* __restrict__ d0,
                      const int* __restrict__ s1, const int* __restrict__ d1,
                      const int* __restrict__ s2, const int* __restrict__ d2,
                      const int* __restrict__ s3, const int* __restrict__ d3) {
    int g = blockIdx.y;
    const int* s = (g == 0) ? s0 : (g == 1) ? s1 : (g == 2) ? s2 : s3;
    const int* d = (g == 0) ? d0 : (g == 1) ? d1 : (g == 2) ? d2 : d3;
    int e = blockIdx.x * blockDim.x + threadIdx.x;
    if (e < EE) {
        atomicAdd(&g_deg_s[g][s[e]], 1);
        atomicAdd(&g_deg_d[g][d[e]], 1);
    }
}

__global__ void k_scan1() {
    int g = blockIdx.y, t = threadIdx.x;
    int i = blockIdx.x * 256 + t;
    __shared__ int sm[256];
    sm[t] = (i < NN) ? g_deg_d[g][i] : 0;
    __syncthreads();
    for (int o = 128; o > 0; o >>= 1) {
        if (t < o) sm[t] += sm[t + o];
        __syncthreads();
    }
    if (t == 0) g_bsum[g][blockIdx.x] = sm[0];
}

__global__ void k_scan2() {
    int g = blockIdx.y, t = threadIdx.x;
    int v = (t < NB) ? g_bsum[g][t] : 0;
    __shared__ int sm[256];
    sm[t] = v;
    __syncthreads();
    for (int o = 1; o < 256; o <<= 1) {
        int a = (t >= o) ? sm[t - o] : 0;
        __syncthreads();
        sm[t] += a;
        __syncthreads();
    }
    g_boff[g][t] = sm[t] - v;  // exclusive
}

__global__ void k_scan3() {
    int g = blockIdx.y, t = threadIdx.x;
    int i = blockIdx.x * 256 + t;
    int d = (i < NN) ? g_deg_d[g][i] : 0;
    __shared__ int sm[256];
    sm[t] = d;
    __syncthreads();
    for (int o = 1; o < 256; o <<= 1) {
        int a = (t >= o) ? sm[t - o] : 0;
        __syncthreads();
        sm[t] += a;
        __syncthreads();
    }
    int off = g_boff[g][blockIdx.x] + sm[t] - d;  // exclusive
    if (i < NN) {
        g_rowoff[g][i] = off;
        g_cursor[g][i] = off;
        g_nd[g][i] = rsqrtf((float)max(d, 1));
        g_ns[g][i] = rsqrtf((float)max(g_deg_s[g][i], 1));
    }
    if (blockIdx.x == 0 && t == 0) g_rowoff[g][NN] = EE;
}

__global__ void k_scatter(const int* __restrict__ s0, const int* __restrict__ d0,
                          const int* __restrict__ s1, const int* __restrict__ d1,
                          const int* __restrict__ s2, const int* __restrict__ d2,
                          const int* __restrict__ s3, const int* __restrict__ d3) {
    int g = blockIdx.y;
    const int* s = (g == 0) ? s0 : (g == 1) ? s1 : (g == 2) ? s2 : s3;
    const int* d = (g == 0) ? d0 : (g == 1) ? d1 : (g == 2) ? d2 : d3;
    int e = blockIdx.x * blockDim.x + threadIdx.x;
    if (e < EE) {
        int p = atomicAdd(&g_cursor[g][d[e]], 1);
        g_csr[g][p] = s[e];
    }
}

// Warp-per-dst SpMM, float4 gathers, bf16x2 output (rows padded to wstride
// words): g_bufAh[n][:] = bf16( nd[n] * sum_{s in in(n)} ns[s]*hin[s][:] )
// Lane l owns float4 slots l, l+32 (F>128), l+64 (l<12).
__global__ void __launch_bounds__(256)
k_spmm(const float* __restrict__ xext, int use_ext, int F, int g, int wstride) {
    const float* __restrict__ hin = use_ext ? xext : (const float*)g_bufB;
    int n = blockIdx.x * 8 + (threadIdx.x >> 5);
    if (n >= NN) return;
    int lane = threadIdx.x & 31;
    int beg = g_rowoff[g][n];
    int end = g_rowoff[g][n + 1];
    float4 a0 = make_float4(0.f, 0.f, 0.f, 0.f);
    float4 a1 = make_float4(0.f, 0.f, 0.f, 0.f);
    float4 a2 = make_float4(0.f, 0.f, 0.f, 0.f);
    int j = beg;
    for (; j + 1 < end; j += 2) {
        int sA = g_csr[g][j], sB = g_csr[g][j + 1];       // broadcast loads
        float wA = g_ns[g][sA], wB = g_ns[g][sB];
        const float4* rA = (const float4*)(hin + (size_t)sA * F);
        const float4* rB = (const float4*)(hin + (size_t)sB * F);
        float4 uA = rA[lane], uB = rB[lane];
        a0.x += wA * uA.x + wB * uB.x;  a0.y += wA * uA.y + wB * uB.y;
        a0.z += wA * uA.z + wB * uB.z;  a0.w += wA * uA.w + wB * uB.w;
        if (F > 128) {
            float4 vA = rA[lane + 32], vB = rB[lane + 32];
            a1.x += wA * vA.x + wB * vB.x;  a1.y += wA * vA.y + wB * vB.y;
            a1.z += wA * vA.z + wB * vB.z;  a1.w += wA * vA.w + wB * vB.w;
            if (lane < 12) {
                float4 tA = rA[lane + 64], tB = rB[lane + 64];
                a2.x += wA * tA.x + wB * tB.x;  a2.y += wA * tA.y + wB * tB.y;
                a2.z += wA * tA.z + wB * tB.z;  a2.w += wA * tA.w + wB * tB.w;
            }
        }
    }
    if (j < end) {
        int s = g_csr[g][j];
        float w = g_ns[g][s];
        const float4* r = (const float4*)(hin + (size_t)s * F);
        float4 u = r[lane];
        a0.x += w * u.x;  a0.y += w * u.y;  a0.z += w * u.z;  a0.w += w * u.w;
        if (F > 128) {
            float4 v = r[lane + 32];
            a1.x += w * v.x;  a1.y += w * v.y;  a1.z += w * v.z;  a1.w += w * v.w;
            if (lane < 12) {
                float4 t2 = r[lane + 64];
                a2.x += w * t2.x;  a2.y += w * t2.y;  a2.z += w * t2.z;  a2.w += w * t2.w;
            }
        }
    }
    float nd = g_nd[g][n];
    uint32_t* o = g_bufAh + (size_t)n * wstride;
    {
        __nv_bfloat162 p0 = __float22bfloat162_rn(make_float2(a0.x * nd, a0.y * nd));
        __nv_bfloat162 p1 = __float22bfloat162_rn(make_float2(a0.z * nd, a0.w * nd));
        *(uint2*)(o + 2 * lane) = make_uint2(*(uint32_t*)&p0, *(uint32_t*)&p1);
    }
    if (F > 128) {
        __nv_bfloat162 p0 = __float22bfloat162_rn(make_float2(a1.x * nd, a1.y * nd));
        __nv_bfloat162 p1 = __float22bfloat162_rn(make_float2(a1.z * nd, a1.w * nd));
        *(uint2*)(o + 64 + 2 * lane) = make_uint2(*(uint32_t*)&p0, *(uint32_t*)&p1);
        if (lane < 12) {
            __nv_bfloat162 q0 = __float22bfloat162_rn(make_float2(a2.x * nd, a2.y * nd));
            __nv_bfloat162 q1 = __float22bfloat162_rn(make_float2(a2.z * nd, a2.w * nd));
            *(uint2*)(o + 128 + 2 * lane) = make_uint2(*(uint32_t*)&q0, *(uint32_t*)&q1);
        } else if (lane < 16) {  // zero the pad words 152..159
            *(uint2*)(o + 128 + 2 * lane) = make_uint2(0u, 0u);
        }
    }
}

// ---------------- bf16 mma.sync GEMM ----------------------------------------
// relu(bf16 A @ Wh^T + bias) -> g_bufB fp32, or (dosum) scalar sum only.
// CTA: 256 thr (8 warps 4x2), tile 128x64, BK=32 (16 bf16x2 words/chunk).
__device__ __forceinline__ void mma16(float* d, const uint32_t* a, const uint32_t* b) {
    asm volatile("mma.sync.aligned.m16n8k16.row.col.f32.bf16.bf16.f32 "
                 "{%0,%1,%2,%3}, {%4,%5,%6,%7}, {%8,%9}, {%0,%1,%2,%3};"
                 : "+f"(d[0]), "+f"(d[1]), "+f"(d[2]), "+f"(d[3])
                 : "r"(a[0]), "r"(a[1]), "r"(a[2]), "r"(a[3]),
                   "r"(b[0]), "r"(b[1]));
}

#define PADW 20  // 16 words + 4 pad

__global__ void __launch_bounds__(256)
k_gemm_mma(const float* __restrict__ bias, int wsel, int NC, int wstride, int dosum) {
    __shared__ uint32_t As[128][PADW];   // bf16x2 words along k
    __shared__ uint32_t Bs[64][PADW];
    __shared__ float wsum[8];

    const uint32_t* __restrict__ Wh = (wsel == 0) ? g_Wh1 : (wsel == 1) ? g_Wh2 : g_Wh3;
    const int Kp2 = NC * 16;   // words per weight row

    int tid = threadIdx.x, wid = tid >> 5, lane = tid & 31;
    int wm = wid & 3, wn = wid >> 2;
    int rowBase = blockIdx.x * 128;
    int colBase = blockIdx.y * 64;

    float acc[2][4][4];
#pragma unroll
    for (int mi = 0; mi < 2; mi++)
#pragma unroll
        for (int ni = 0; ni < 4; ni++)
#pragma unroll
            for (int q = 0; q < 4; q++) acc[mi][ni][q] = 0.f;

    int ar = tid >> 2, aw = tid & 3;     // A: rows ar, ar+64; uint4 col aw
    int br = tid >> 2, bw = tid & 3;     // B: row br; uint4 col bw
    uint4 aU[2], bU;

    {   // prefetch chunk 0
#pragma unroll
        for (int j = 0; j < 2; j++) {
            int gr = rowBase + ar + j * 64;
            aU[j] = (gr < NN)
                ? *(const uint4*)(g_bufAh + (size_t)gr * wstride + aw * 4)
                : make_uint4(0u, 0u, 0u, 0u);
        }
        bU = *(const uint4*)(Wh + (size_t)(colBase + br) * Kp2 + bw * 4);
    }

    for (int c = 0; c < NC; c++) {
#pragma unroll
        for (int j = 0; j < 2; j++)
            *(uint4*)&As[ar + j * 64][aw * 4] = aU[j];
        *(uint4*)&Bs[br][bw * 4] = bU;
        __syncthreads();

        if (c + 1 < NC) {
            int kw0 = (c + 1) * 16;
#pragma unroll
            for (int j = 0; j < 2; j++) {
                int gr = rowBase + ar + j * 64;
                aU[j] = (gr < NN)
                    ? *(const uint4*)(g_bufAh + (size_t)gr * wstride + kw0 + aw * 4)
                    : make_uint4(0u, 0u, 0u, 0u);
            }
            bU = *(const uint4*)(Wh + (size_t)(colBase + br) * Kp2 + kw0 + bw * 4);
        }

        int g = lane >> 2, cc = lane & 3;
#pragma unroll
        for (int kw = 0; kw < 16; kw += 8) {
            uint32_t af[2][4], bf[4][2];
#pragma unroll
            for (int mi = 0; mi < 2; mi++) {
                int base = wm * 32 + mi * 16 + g;
                af[mi][0] = As[base][kw + cc];
                af[mi][1] = As[base + 8][kw + cc];
                af[mi][2] = As[base][kw + cc + 4];
                af[mi][3] = As[base + 8][kw + cc + 4];
            }
#pragma unroll
            for (int ni = 0; ni < 4; ni++) {
                int nb = wn * 32 + ni * 8 + g;
                bf[ni][0] = Bs[nb][kw + cc];
                bf[ni][1] = Bs[nb][kw + cc + 4];
            }
#pragma unroll
            for (int mi = 0; mi < 2; mi++)
#pragma unroll
                for (int ni = 0; ni < 4; ni++)
                    mma16(acc[mi][ni], af[mi], bf[ni]);
        }
        __syncthreads();
    }

    // epilogue: bias + relu; store fp32 (layers 1-2) or scalar sum only (layer 3)
    float lsum = 0.f;
    int g = lane >> 2, cc = lane & 3;
#pragma unroll
    for (int mi = 0; mi < 2; mi++) {
        int r0 = rowBase + wm * 32 + mi * 16 + g;
#pragma unroll
        for (int ni = 0; ni < 4; ni++) {
            int c0 = colBase + wn * 32 + ni * 8 + cc * 2;
            if (c0 < FH) {
                float bz0 = bias[c0], bz1 = bias[c0 + 1];
                float v0 = fmaxf(acc[mi][ni][0] + bz0, 0.f);
                float v1 = fmaxf(acc[mi][ni][1] + bz1, 0.f);
                float v2 = fmaxf(acc[mi][ni][2] + bz0, 0.f);
                float v3 = fmaxf(acc[mi][ni][3] + bz1, 0.f);
                if (dosum) {
                    if (r0 < NN)     lsum += v0 + v1;
                    if (r0 + 8 < NN) lsum += v2 + v3;
                } else {
                    if (r0 < NN)
                        *(float2*)(g_bufB + (size_t)r0 * FH + c0) = make_float2(v0, v1);
                    if (r0 + 8 < NN)
                        *(float2*)(g_bufB + (size_t)(r0 + 8) * FH + c0) = make_float2(v2, v3);
                }
            }
        }
    }
    if (dosum) {
#pragma unroll
        for (int o = 16; o > 0; o >>= 1) lsum += __shfl_down_sync(0xffffffffu, lsum, o);
        if (lane == 0) wsum[wid] = lsum;
        __syncthreads();
        if (tid == 0) {
            double tot = 0.0;
#pragma unroll
            for (int w = 0; w < 8; w++) tot += (double)wsum[w];
            atomicAdd(&g_sum, tot);
        }
    }
}

__global__ void k_final(float* __restrict__ out) {
    out[0] = (float)(g_sum / (4.0 * NN * FH));
}

// ---------------- launch -----------------------------------------------------
extern "C" void kernel_launch(void* const* d_in, const int* in_sizes, int n_in,
                              void* d_out, int out_size) {
    const float* X[4];   int nx = 0;
    const int*   EDG[8]; int ne = 0;
    const float* W[3] = {0, 0, 0};
    const float* Bv[3]; int nb = 0;
    int nw2 = 0;
    for (int i = 0; i < n_in; i++) {
        int sz = in_sizes[i];
        if (sz == 6400000)      X[nx++]   = (const float*)d_in[i];
        else if (sz == 800000)  EDG[ne++] = (const int*)d_in[i];
        else if (sz == 38912)   W[0] = (const float*)d_in[i];
        else if (sz == 92416)   { W[1 + nw2] = (const float*)d_in[i]; nw2++; }
        else if (sz == 304)     Bv[nb++] = (const float*)d_in[i];
    }
    float* out = (float*)d_out;

    k_init<<<1, 1>>>();
    k_prep_wh<<<(320 * 64 + 255) / 256, 256>>>(W[0], 0, 128, 64);
    k_prep_wh<<<(320 * 160 + 255) / 256, 256>>>(W[1], 1, 304, 160);
    k_prep_wh<<<(320 * 160 + 255) / 256, 256>>>(W[2], 2, 304, 160);

    // batched CSR build for all 4 graphs
    k_zero<<<dim3(NB, NG), 256>>>();
    k_deg<<<dim3(EE / 256, NG), 256>>>(EDG[0], EDG[1], EDG[2], EDG[3],
                                       EDG[4], EDG[5], EDG[6], EDG[7]);
    k_scan1<<<dim3(NB, NG), 256>>>();
    k_scan2<<<dim3(1, NG), 256>>>();
    k_scan3<<<dim3(NB, NG), 256>>>();
    k_scatter<<<dim3(EE / 256, NG), 256>>>(EDG[0], EDG[1], EDG[2], EDG[3],
                                           EDG[4], EDG[5], EDG[6], EDG[7]);

    dim3 gemmGrid((NN + 127) / 128, 5);  // N padded to 320
    const int spmmGrid = NN / 8;         // 6250 blocks x 8 warps
    for (int g = 0; g < 4; g++) {
        k_spmm<<<spmmGrid, 256>>>(X[g], 1, FI, g, 64);
        k_gemm_mma<<<gemmGrid, 256>>>(Bv[0], 0, 4, 64, 0);
        k_spmm<<<spmmGrid, 256>>>(X[g], 0, FH, g, 160);
        k_gemm_mma<<<gemmGrid, 256>>>(Bv[1], 1, 10, 160, 0);
        k_spmm<<<spmmGrid, 256>>>(X[g], 0, FH, g, 160);
        k_gemm_mma<<<gemmGrid, 256>>>(Bv[2], 2, 10, 160, 1);
    }
    k_final<<<1, 1>>>(out);
}